// round 3
// baseline (speedup 1.0000x reference)
#include <cuda_runtime.h>

#define IN_CH 65
#define HID   64
#define MAX_NODES 100000
#define MAX_EDGES 3200000

// ---------------------------------------------------------------------------
// Static scratch (no allocations allowed)
// ---------------------------------------------------------------------------
__device__ float g_y[(size_t)MAX_NODES * HID];          // y = x @ W_rel^T
__device__ int   g_deg[MAX_NODES];                      // in-degree histogram
__device__ int   g_offs[MAX_NODES + 1];                 // CSR row offsets
__device__ int   g_cursor[MAX_NODES];                   // fill cursors
__device__ int2  g_entries[MAX_EDGES];                  // (src, bits(w)) sorted by dst

// ---------------------------------------------------------------------------
// Kernel 1: per-node dual matvec, 2 nodes per iteration for 4 FMA chains/warp.
//   g_y[n] = W_rel @ x[n];  out[n] = W_root @ x[n] + b_rel
// ---------------------------------------------------------------------------
__global__ __launch_bounds__(64) void transform_kernel(
    const float* __restrict__ x,
    const float* __restrict__ W_rel,
    const float* __restrict__ b_rel,
    const float* __restrict__ W_root,
    float* __restrict__ out,
    int n_nodes)
{
    const int o = threadIdx.x;  // 0..63 output channel

    float wr[IN_CH], wo[IN_CH];
#pragma unroll
    for (int k = 0; k < IN_CH; ++k) {
        wr[k] = W_rel[o * IN_CH + k];
        wo[k] = W_root[o * IN_CH + k];
    }
    const float bias = b_rel[o];

    __shared__ float sx[2][IN_CH];

    const int stride = gridDim.x * 2;
    for (int n0 = blockIdx.x * 2; n0 < n_nodes; n0 += stride) {
        const int n1 = n0 + 1;
        const bool has1 = (n1 < n_nodes);

        const float* xr0 = x + (size_t)n0 * IN_CH;
        sx[0][o] = xr0[o];
        if (o == 0) sx[0][64] = xr0[64];
        if (has1) {
            const float* xr1 = x + (size_t)n1 * IN_CH;
            sx[1][o] = xr1[o];
            if (o == 0) sx[1][64] = xr1[64];
        }
        __syncthreads();

        float ay0 = 0.0f, ao0 = bias;
        float ay1 = 0.0f, ao1 = bias;
#pragma unroll
        for (int k = 0; k < IN_CH; ++k) {
            const float x0 = sx[0][k];
            const float x1 = sx[1][k];
            ay0 = fmaf(wr[k], x0, ay0);
            ao0 = fmaf(wo[k], x0, ao0);
            ay1 = fmaf(wr[k], x1, ay1);
            ao1 = fmaf(wo[k], x1, ao1);
        }
        g_y[(size_t)n0 * HID + o] = ay0;
        out[(size_t)n0 * HID + o] = ao0;
        if (has1) {
            g_y[(size_t)n1 * HID + o] = ay1;
            out[(size_t)n1 * HID + o] = ao1;
        }
        __syncthreads();
    }
}

// ---------------------------------------------------------------------------
// Kernel 2: zero the degree histogram (graph replays require re-init).
// ---------------------------------------------------------------------------
__global__ void zero_kernel(int n_nodes)
{
    const int i = blockIdx.x * blockDim.x + threadIdx.x;
    if (i < n_nodes) g_deg[i] = 0;
}

// ---------------------------------------------------------------------------
// Kernel 3: in-degree histogram. RED.ADD to 400KB of counters (L2-resident).
// ---------------------------------------------------------------------------
__global__ void hist_kernel(const int* __restrict__ ei, int E)
{
    const int e = blockIdx.x * blockDim.x + threadIdx.x;
    if (e < E) atomicAdd(&g_deg[ei[E + e]], 1);
}

// ---------------------------------------------------------------------------
// Kernel 4: exclusive scan of g_deg -> g_offs / g_cursor. Single block,
// shfl warp-scans + cross-warp scan, sequential 1024-wide chunks with carry.
// ---------------------------------------------------------------------------
__global__ __launch_bounds__(1024) void scan_kernel(int n_nodes)
{
    __shared__ int ws[32];
    __shared__ int carry_s;
    const int tid  = threadIdx.x;
    const int lane = tid & 31;
    const int wid  = tid >> 5;

    if (tid == 0) carry_s = 0;
    __syncthreads();

    for (int base = 0; base < n_nodes; base += 1024) {
        const int i = base + tid;
        const int v = (i < n_nodes) ? g_deg[i] : 0;

        // inclusive warp scan
        int xv = v;
#pragma unroll
        for (int d = 1; d < 32; d <<= 1) {
            int t = __shfl_up_sync(0xffffffffu, xv, d);
            if (lane >= d) xv += t;
        }
        if (lane == 31) ws[wid] = xv;
        __syncthreads();
        if (wid == 0) {
            int y = ws[lane];
#pragma unroll
            for (int d = 1; d < 32; d <<= 1) {
                int t = __shfl_up_sync(0xffffffffu, y, d);
                if (lane >= d) y += t;
            }
            ws[lane] = y;
        }
        __syncthreads();

        const int incl = xv + (wid ? ws[wid - 1] : 0);
        const int excl = incl - v + carry_s;
        if (i < n_nodes) { g_offs[i] = excl; g_cursor[i] = excl; }
        __syncthreads();                 // all carry_s reads done
        if (tid == 1023) carry_s += ws[31];
        __syncthreads();
    }
    if (tid == 0) g_offs[n_nodes] = carry_s;
}

// ---------------------------------------------------------------------------
// Kernel 5: counting-sort fill. entries[pos] = (src, bits(w)), grouped by dst.
// ---------------------------------------------------------------------------
__global__ void fill_kernel(const int* __restrict__ ei,
                            const float* __restrict__ ew, int E)
{
    const int e = blockIdx.x * blockDim.x + threadIdx.x;
    if (e >= E) return;
    const int dst = ei[E + e];
    const int pos = atomicAdd(&g_cursor[dst], 1);
    g_entries[pos] = make_int2(ei[e], __float_as_int(ew[e]));
}

// ---------------------------------------------------------------------------
// Kernel 6: atomic-free aggregation. A 16-lane half-warp exclusively owns one
// node: loops its CSR range, float4-gathers the y row of each source node,
// accumulates in registers, then one plain read-modify-write into out
// (which already holds W_root@x + b from the transform kernel).
// ---------------------------------------------------------------------------
__global__ __launch_bounds__(256) void aggregate_kernel(
    float* __restrict__ out, int n_nodes)
{
    const int tid  = threadIdx.x;
    const int sub  = tid & 15;                       // channel chunk 0..15
    const int half = tid >> 4;                       // half-warp slot 0..15
    const int n    = blockIdx.x * 16 + half;
    if (n >= n_nodes) return;

    const int start = g_offs[n];
    const int end   = g_offs[n + 1];

    float4 acc = make_float4(0.f, 0.f, 0.f, 0.f);

    int j = start;
    // unroll-by-2 for memory-level parallelism
    for (; j + 1 < end; j += 2) {
        const int2 e0 = __ldg(&g_entries[j]);
        const int2 e1 = __ldg(&g_entries[j + 1]);
        const float w0 = __int_as_float(e0.y);
        const float w1 = __int_as_float(e1.y);
        const float4 v0 = *reinterpret_cast<const float4*>(
            g_y + (size_t)e0.x * HID + sub * 4);
        const float4 v1 = *reinterpret_cast<const float4*>(
            g_y + (size_t)e1.x * HID + sub * 4);
        acc.x = fmaf(w0, v0.x, acc.x); acc.y = fmaf(w0, v0.y, acc.y);
        acc.z = fmaf(w0, v0.z, acc.z); acc.w = fmaf(w0, v0.w, acc.w);
        acc.x = fmaf(w1, v1.x, acc.x); acc.y = fmaf(w1, v1.y, acc.y);
        acc.z = fmaf(w1, v1.z, acc.z); acc.w = fmaf(w1, v1.w, acc.w);
    }
    if (j < end) {
        const int2 e0 = __ldg(&g_entries[j]);
        const float w0 = __int_as_float(e0.y);
        const float4 v0 = *reinterpret_cast<const float4*>(
            g_y + (size_t)e0.x * HID + sub * 4);
        acc.x = fmaf(w0, v0.x, acc.x); acc.y = fmaf(w0, v0.y, acc.y);
        acc.z = fmaf(w0, v0.z, acc.z); acc.w = fmaf(w0, v0.w, acc.w);
    }

    float4* p = reinterpret_cast<float4*>(out + (size_t)n * HID + sub * 4);
    float4 o = *p;
    o.x += acc.x; o.y += acc.y; o.z += acc.z; o.w += acc.w;
    *p = o;
}

// ---------------------------------------------------------------------------
extern "C" void kernel_launch(void* const* d_in, const int* in_sizes, int n_in,
                              void* d_out, int out_size)
{
    const float* x      = (const float*)d_in[0];
    const int*   ei     = (const int*)d_in[1];
    const float* ew     = (const float*)d_in[2];
    const float* W_rel  = (const float*)d_in[3];
    const float* b_rel  = (const float*)d_in[4];
    const float* W_root = (const float*)d_in[5];
    float*       out    = (float*)d_out;

    const int n_nodes = in_sizes[0] / IN_CH;
    const int E       = in_sizes[1] / 2;   // edge_index is [2, E] int32

    const int eb = (E + 255) / 256;

    // out = W_root@x + b ; y = W_rel@x
    transform_kernel<<<2048, 64>>>(x, W_rel, b_rel, W_root, out, n_nodes);
    // CSR build
    zero_kernel<<<(n_nodes + 255) / 256, 256>>>(n_nodes);
    hist_kernel<<<eb, 256>>>(ei, E);
    scan_kernel<<<1, 1024>>>(n_nodes);
    fill_kernel<<<eb, 256>>>(ei, ew, E);
    // out[n] += sum_{e: dst=n} w_e * y[src_e]
    aggregate_kernel<<<(n_nodes + 15) / 16, 256>>>(out, n_nodes);
}

// round 4
// speedup vs baseline: 1.2574x; 1.2574x over previous
#include <cuda_runtime.h>

#define IN_CH 65
#define HID   64
#define MAX_NODES 100000
#define MAX_EDGES 3200000
#define SCAN_BLK  1024
#define MAX_SBLKS ((MAX_NODES + SCAN_BLK - 1) / SCAN_BLK)   // 98

// ---------------------------------------------------------------------------
// Static scratch (no allocations allowed)
// ---------------------------------------------------------------------------
__device__ float g_y[(size_t)MAX_NODES * HID];          // y = x @ W_rel^T
__device__ int   g_deg[MAX_NODES];                      // in-degree histogram
__device__ int   g_offs[MAX_NODES + 1];                 // CSR row offsets
__device__ int   g_cursor[MAX_NODES];                   // fill cursors
__device__ int   g_bsum[MAX_SBLKS];                     // per-block scan sums
__device__ int2  g_entries[MAX_EDGES];                  // (src, bits(w)) sorted by dst

// ---------------------------------------------------------------------------
// Kernel 1: per-node dual matvec, 2 nodes per iteration for 4 FMA chains/warp.
// ---------------------------------------------------------------------------
__global__ __launch_bounds__(64) void transform_kernel(
    const float* __restrict__ x,
    const float* __restrict__ W_rel,
    const float* __restrict__ b_rel,
    const float* __restrict__ W_root,
    float* __restrict__ out,
    int n_nodes)
{
    const int o = threadIdx.x;  // 0..63 output channel

    float wr[IN_CH], wo[IN_CH];
#pragma unroll
    for (int k = 0; k < IN_CH; ++k) {
        wr[k] = W_rel[o * IN_CH + k];
        wo[k] = W_root[o * IN_CH + k];
    }
    const float bias = b_rel[o];

    __shared__ float sx[2][IN_CH];

    const int stride = gridDim.x * 2;
    for (int n0 = blockIdx.x * 2; n0 < n_nodes; n0 += stride) {
        const int n1 = n0 + 1;
        const bool has1 = (n1 < n_nodes);

        const float* xr0 = x + (size_t)n0 * IN_CH;
        sx[0][o] = xr0[o];
        if (o == 0) sx[0][64] = xr0[64];
        if (has1) {
            const float* xr1 = x + (size_t)n1 * IN_CH;
            sx[1][o] = xr1[o];
            if (o == 0) sx[1][64] = xr1[64];
        }
        __syncthreads();

        float ay0 = 0.0f, ao0 = bias;
        float ay1 = 0.0f, ao1 = bias;
#pragma unroll
        for (int k = 0; k < IN_CH; ++k) {
            const float x0 = sx[0][k];
            const float x1 = sx[1][k];
            ay0 = fmaf(wr[k], x0, ay0);
            ao0 = fmaf(wo[k], x0, ao0);
            ay1 = fmaf(wr[k], x1, ay1);
            ao1 = fmaf(wo[k], x1, ao1);
        }
        g_y[(size_t)n0 * HID + o] = ay0;
        out[(size_t)n0 * HID + o] = ao0;
        if (has1) {
            g_y[(size_t)n1 * HID + o] = ay1;
            out[(size_t)n1 * HID + o] = ao1;
        }
        __syncthreads();
    }
}

// ---------------------------------------------------------------------------
// Kernel 2: zero the degree histogram (graph replays require re-init).
// ---------------------------------------------------------------------------
__global__ void zero_kernel(int n_nodes)
{
    const int i = blockIdx.x * blockDim.x + threadIdx.x;
    if (i < n_nodes) g_deg[i] = 0;
}

// ---------------------------------------------------------------------------
// Kernel 3: in-degree histogram. RED.ADD to 400KB of counters (L2-resident).
// ---------------------------------------------------------------------------
__global__ void hist_kernel(const int* __restrict__ ei, int E)
{
    const int e = blockIdx.x * blockDim.x + threadIdx.x;
    if (e < E) atomicAdd(&g_deg[ei[E + e]], 1);
}

// ---------------------------------------------------------------------------
// Scan phase 1: per-block exclusive scan. Block b handles elements
// [b*1024, b*1024+1024). Writes partial exclusive values to g_offs and the
// block total to g_bsum[b].
// ---------------------------------------------------------------------------
__global__ __launch_bounds__(SCAN_BLK) void scan1_kernel(int n_nodes)
{
    __shared__ int ws[32];
    const int tid  = threadIdx.x;
    const int lane = tid & 31;
    const int wid  = tid >> 5;
    const int i    = blockIdx.x * SCAN_BLK + tid;

    const int v = (i < n_nodes) ? g_deg[i] : 0;

    int xv = v;
#pragma unroll
    for (int d = 1; d < 32; d <<= 1) {
        int t = __shfl_up_sync(0xffffffffu, xv, d);
        if (lane >= d) xv += t;
    }
    if (lane == 31) ws[wid] = xv;
    __syncthreads();
    if (wid == 0) {
        int y = ws[lane];
#pragma unroll
        for (int d = 1; d < 32; d <<= 1) {
            int t = __shfl_up_sync(0xffffffffu, y, d);
            if (lane >= d) y += t;
        }
        ws[lane] = y;
    }
    __syncthreads();

    const int incl = xv + (wid ? ws[wid - 1] : 0);
    if (i < n_nodes) g_offs[i] = incl - v;          // partial exclusive
    if (tid == SCAN_BLK - 1) g_bsum[blockIdx.x] = incl;
}

// ---------------------------------------------------------------------------
// Scan phase 2: one block turns g_bsum into its exclusive scan (<=1024 blocks).
// ---------------------------------------------------------------------------
__global__ __launch_bounds__(SCAN_BLK) void scan2_kernel(int n_sblks)
{
    __shared__ int ws[32];
    const int tid  = threadIdx.x;
    const int lane = tid & 31;
    const int wid  = tid >> 5;

    const int v = (tid < n_sblks) ? g_bsum[tid] : 0;

    int xv = v;
#pragma unroll
    for (int d = 1; d < 32; d <<= 1) {
        int t = __shfl_up_sync(0xffffffffu, xv, d);
        if (lane >= d) xv += t;
    }
    if (lane == 31) ws[wid] = xv;
    __syncthreads();
    if (wid == 0) {
        int y = ws[lane];
#pragma unroll
        for (int d = 1; d < 32; d <<= 1) {
            int t = __shfl_up_sync(0xffffffffu, y, d);
            if (lane >= d) y += t;
        }
        ws[lane] = y;
    }
    __syncthreads();

    const int incl = xv + (wid ? ws[wid - 1] : 0);
    if (tid < n_sblks) g_bsum[tid] = incl - v;      // exclusive block offset
}

// ---------------------------------------------------------------------------
// Scan phase 3: finalize offsets, init cursors, set sentinel.
// ---------------------------------------------------------------------------
__global__ void scan3_kernel(int n_nodes, int E)
{
    const int i = blockIdx.x * blockDim.x + threadIdx.x;
    if (i < n_nodes) {
        const int off = g_offs[i] + g_bsum[i >> 10];
        g_offs[i]   = off;
        g_cursor[i] = off;
    }
    if (i == 0) g_offs[n_nodes] = E;
}

// ---------------------------------------------------------------------------
// Kernel 5: counting-sort fill. entries[pos] = (src, bits(w)), grouped by dst.
// ---------------------------------------------------------------------------
__global__ void fill_kernel(const int* __restrict__ ei,
                            const float* __restrict__ ew, int E)
{
    const int e = blockIdx.x * blockDim.x + threadIdx.x;
    if (e >= E) return;
    const int dst = ei[E + e];
    const int pos = atomicAdd(&g_cursor[dst], 1);
    g_entries[pos] = make_int2(ei[e], __float_as_int(ew[e]));
}

// ---------------------------------------------------------------------------
// Kernel 6: atomic-free aggregation. A 16-lane half-warp exclusively owns one
// node: loops its CSR range, float4-gathers the y row of each source node,
// accumulates in registers, one plain RMW into out.
// ---------------------------------------------------------------------------
__global__ __launch_bounds__(256) void aggregate_kernel(
    float* __restrict__ out, int n_nodes)
{
    const int tid  = threadIdx.x;
    const int sub  = tid & 15;                       // channel chunk 0..15
    const int half = tid >> 4;                       // half-warp slot 0..15
    const int n    = blockIdx.x * 16 + half;
    if (n >= n_nodes) return;

    const int start = g_offs[n];
    const int end   = g_offs[n + 1];

    float4 acc = make_float4(0.f, 0.f, 0.f, 0.f);

    int j = start;
    for (; j + 1 < end; j += 2) {
        const int2 e0 = __ldg(&g_entries[j]);
        const int2 e1 = __ldg(&g_entries[j + 1]);
        const float w0 = __int_as_float(e0.y);
        const float w1 = __int_as_float(e1.y);
        const float4 v0 = *reinterpret_cast<const float4*>(
            g_y + (size_t)e0.x * HID + sub * 4);
        const float4 v1 = *reinterpret_cast<const float4*>(
            g_y + (size_t)e1.x * HID + sub * 4);
        acc.x = fmaf(w0, v0.x, acc.x); acc.y = fmaf(w0, v0.y, acc.y);
        acc.z = fmaf(w0, v0.z, acc.z); acc.w = fmaf(w0, v0.w, acc.w);
        acc.x = fmaf(w1, v1.x, acc.x); acc.y = fmaf(w1, v1.y, acc.y);
        acc.z = fmaf(w1, v1.z, acc.z); acc.w = fmaf(w1, v1.w, acc.w);
    }
    if (j < end) {
        const int2 e0 = __ldg(&g_entries[j]);
        const float w0 = __int_as_float(e0.y);
        const float4 v0 = *reinterpret_cast<const float4*>(
            g_y + (size_t)e0.x * HID + sub * 4);
        acc.x = fmaf(w0, v0.x, acc.x); acc.y = fmaf(w0, v0.y, acc.y);
        acc.z = fmaf(w0, v0.z, acc.z); acc.w = fmaf(w0, v0.w, acc.w);
    }

    float4* p = reinterpret_cast<float4*>(out + (size_t)n * HID + sub * 4);
    float4 o = *p;
    o.x += acc.x; o.y += acc.y; o.z += acc.z; o.w += acc.w;
    *p = o;
}

// ---------------------------------------------------------------------------
extern "C" void kernel_launch(void* const* d_in, const int* in_sizes, int n_in,
                              void* d_out, int out_size)
{
    const float* x      = (const float*)d_in[0];
    const int*   ei     = (const int*)d_in[1];
    const float* ew     = (const float*)d_in[2];
    const float* W_rel  = (const float*)d_in[3];
    const float* b_rel  = (const float*)d_in[4];
    const float* W_root = (const float*)d_in[5];
    float*       out    = (float*)d_out;

    const int n_nodes = in_sizes[0] / IN_CH;
    const int E       = in_sizes[1] / 2;   // edge_index is [2, E] int32

    const int eb      = (E + 255) / 256;
    const int n_sblks = (n_nodes + SCAN_BLK - 1) / SCAN_BLK;

    // out = W_root@x + b ; y = W_rel@x
    transform_kernel<<<2048, 64>>>(x, W_rel, b_rel, W_root, out, n_nodes);
    // CSR build
    zero_kernel<<<(n_nodes + 255) / 256, 256>>>(n_nodes);
    hist_kernel<<<eb, 256>>>(ei, E);
    scan1_kernel<<<n_sblks, SCAN_BLK>>>(n_nodes);
    scan2_kernel<<<1, SCAN_BLK>>>(n_sblks);
    scan3_kernel<<<(n_nodes + 255) / 256, 256>>>(n_nodes, E);
    fill_kernel<<<eb, 256>>>(ei, ew, E);
    // out[n] += sum_{e: dst=n} w_e * y[src_e]
    aggregate_kernel<<<(n_nodes + 15) / 16, 256>>>(out, n_nodes);
}

// round 5
// speedup vs baseline: 1.2815x; 1.0191x over previous
#include <cuda_runtime.h>

#define IN_CH 65
#define HID   64
#define NPAIR 33   // ceil(65/2) packed k-pairs
#define MAX_NODES 100000
#define MAX_EDGES 3200000
#define SCAN_BLK  1024
#define MAX_SBLKS ((MAX_NODES + SCAN_BLK - 1) / SCAN_BLK)   // 98

typedef unsigned long long ull;

// ---------------------------------------------------------------------------
// Static scratch (no allocations allowed)
// ---------------------------------------------------------------------------
__device__ float g_y[(size_t)MAX_NODES * HID];          // y = x @ W_rel^T
__device__ int   g_deg[MAX_NODES];                      // in-degree histogram
__device__ int   g_offs[MAX_NODES + 1];                 // CSR row offsets
__device__ int   g_cursor[MAX_NODES];                   // fill cursors
__device__ int   g_bsum[MAX_SBLKS];                     // per-block scan sums
__device__ int2  g_entries[MAX_EDGES];                  // (src, bits(w)) sorted by dst

// ---------------------------------------------------------------------------
// Packed f32x2 helpers (Blackwell FFMA2 — only reachable via PTX)
// ---------------------------------------------------------------------------
__device__ __forceinline__ ull pack_f32x2(float lo, float hi) {
    ull r;
    asm("mov.b64 %0, {%1, %2};" : "=l"(r) : "f"(lo), "f"(hi));
    return r;
}
__device__ __forceinline__ void unpack_f32x2(ull v, float& lo, float& hi) {
    asm("mov.b64 {%0, %1}, %2;" : "=f"(lo), "=f"(hi) : "l"(v));
}
__device__ __forceinline__ void fma_f32x2(ull& d, ull a, ull b) {
    asm("fma.rn.f32x2 %0, %1, %2, %0;" : "+l"(d) : "l"(a), "l"(b));
}

// ---------------------------------------------------------------------------
// Kernel 1: per-node dual matvec, 2 nodes/iter, packed f32x2 FMA over k-pairs.
//   g_y[n] = W_rel @ x[n];  out[n] = W_root @ x[n] + b_rel
// Thread o owns output channel o. Weights held as packed b64 registers.
// ---------------------------------------------------------------------------
__global__ __launch_bounds__(64) void transform_kernel(
    const float* __restrict__ x,
    const float* __restrict__ W_rel,
    const float* __restrict__ b_rel,
    const float* __restrict__ W_root,
    float* __restrict__ out,
    int n_nodes)
{
    const int o = threadIdx.x;  // 0..63 output channel

    // Packed weights: pair p = (W[o][2p], W[o][2p+1]); last pair zero-padded.
    ull wrp[NPAIR], wop[NPAIR];
#pragma unroll
    for (int p = 0; p < NPAIR; ++p) {
        const int k0 = 2 * p, k1 = 2 * p + 1;
        const float r0 = W_rel[o * IN_CH + k0];
        const float r1 = (k1 < IN_CH) ? W_rel[o * IN_CH + k1] : 0.0f;
        const float o0 = W_root[o * IN_CH + k0];
        const float o1 = (k1 < IN_CH) ? W_root[o * IN_CH + k1] : 0.0f;
        wrp[p] = pack_f32x2(r0, r1);
        wop[p] = pack_f32x2(o0, o1);
    }
    const float bias = b_rel[o];

    // 68-float rows: 16B-aligned, slots 65..67 padding (65 zeroed once).
    __shared__ __align__(16) float sx[2][68];
    if (o < 2) { sx[o][65] = 0.0f; sx[o][66] = 0.0f; sx[o][67] = 0.0f; }

    const int stride = gridDim.x * 2;
    for (int n0 = blockIdx.x * 2; n0 < n_nodes; n0 += stride) {
        const int n1 = n0 + 1;
        const bool has1 = (n1 < n_nodes);

        const float* xr0 = x + (size_t)n0 * IN_CH;
        sx[0][o] = xr0[o];
        if (o == 0) sx[0][64] = xr0[64];
        if (has1) {
            const float* xr1 = x + (size_t)n1 * IN_CH;
            sx[1][o] = xr1[o];
            if (o == 0) sx[1][64] = xr1[64];
        }
        __syncthreads();

        const ull* sp0 = reinterpret_cast<const ull*>(sx[0]);
        const ull* sp1 = reinterpret_cast<const ull*>(sx[1]);

        ull accY0 = 0ull, accO0 = 0ull, accY1 = 0ull, accO1 = 0ull;
#pragma unroll
        for (int p = 0; p < NPAIR; ++p) {
            const ull x0 = sp0[p];
            const ull x1 = sp1[p];
            fma_f32x2(accY0, wrp[p], x0);
            fma_f32x2(accO0, wop[p], x0);
            fma_f32x2(accY1, wrp[p], x1);
            fma_f32x2(accO1, wop[p], x1);
        }

        float lo, hi;
        unpack_f32x2(accY0, lo, hi);
        g_y[(size_t)n0 * HID + o] = lo + hi;
        unpack_f32x2(accO0, lo, hi);
        out[(size_t)n0 * HID + o] = lo + hi + bias;
        if (has1) {
            unpack_f32x2(accY1, lo, hi);
            g_y[(size_t)n1 * HID + o] = lo + hi;
            unpack_f32x2(accO1, lo, hi);
            out[(size_t)n1 * HID + o] = lo + hi + bias;
        }
        __syncthreads();
    }
}

// ---------------------------------------------------------------------------
// Kernel 2: zero the degree histogram (graph replays require re-init).
// ---------------------------------------------------------------------------
__global__ void zero_kernel(int n_nodes)
{
    const int i = blockIdx.x * blockDim.x + threadIdx.x;
    if (i < n_nodes) g_deg[i] = 0;
}

// ---------------------------------------------------------------------------
// Kernel 3: in-degree histogram. RED.ADD to 400KB of counters (L2-resident).
// ---------------------------------------------------------------------------
__global__ void hist_kernel(const int* __restrict__ ei, int E)
{
    const int e = blockIdx.x * blockDim.x + threadIdx.x;
    if (e < E) atomicAdd(&g_deg[ei[E + e]], 1);
}

// ---------------------------------------------------------------------------
// Scan phase 1: per-block exclusive scan; block total to g_bsum.
// ---------------------------------------------------------------------------
__global__ __launch_bounds__(SCAN_BLK) void scan1_kernel(int n_nodes)
{
    __shared__ int ws[32];
    const int tid  = threadIdx.x;
    const int lane = tid & 31;
    const int wid  = tid >> 5;
    const int i    = blockIdx.x * SCAN_BLK + tid;

    const int v = (i < n_nodes) ? g_deg[i] : 0;

    int xv = v;
#pragma unroll
    for (int d = 1; d < 32; d <<= 1) {
        int t = __shfl_up_sync(0xffffffffu, xv, d);
        if (lane >= d) xv += t;
    }
    if (lane == 31) ws[wid] = xv;
    __syncthreads();
    if (wid == 0) {
        int y = ws[lane];
#pragma unroll
        for (int d = 1; d < 32; d <<= 1) {
            int t = __shfl_up_sync(0xffffffffu, y, d);
            if (lane >= d) y += t;
        }
        ws[lane] = y;
    }
    __syncthreads();

    const int incl = xv + (wid ? ws[wid - 1] : 0);
    if (i < n_nodes) g_offs[i] = incl - v;          // partial exclusive
    if (tid == SCAN_BLK - 1) g_bsum[blockIdx.x] = incl;
}

// ---------------------------------------------------------------------------
// Scan phase 2: one block scans the (<=1024) block sums.
// ---------------------------------------------------------------------------
__global__ __launch_bounds__(SCAN_BLK) void scan2_kernel(int n_sblks)
{
    __shared__ int ws[32];
    const int tid  = threadIdx.x;
    const int lane = tid & 31;
    const int wid  = tid >> 5;

    const int v = (tid < n_sblks) ? g_bsum[tid] : 0;

    int xv = v;
#pragma unroll
    for (int d = 1; d < 32; d <<= 1) {
        int t = __shfl_up_sync(0xffffffffu, xv, d);
        if (lane >= d) xv += t;
    }
    if (lane == 31) ws[wid] = xv;
    __syncthreads();
    if (wid == 0) {
        int y = ws[lane];
#pragma unroll
        for (int d = 1; d < 32; d <<= 1) {
            int t = __shfl_up_sync(0xffffffffu, y, d);
            if (lane >= d) y += t;
        }
        ws[lane] = y;
    }
    __syncthreads();

    const int incl = xv + (wid ? ws[wid - 1] : 0);
    if (tid < n_sblks) g_bsum[tid] = incl - v;      // exclusive block offset
}

// ---------------------------------------------------------------------------
// Scan phase 3: finalize offsets, init cursors, set sentinel.
// ---------------------------------------------------------------------------
__global__ void scan3_kernel(int n_nodes, int E)
{
    const int i = blockIdx.x * blockDim.x + threadIdx.x;
    if (i < n_nodes) {
        const int off = g_offs[i] + g_bsum[i >> 10];
        g_offs[i]   = off;
        g_cursor[i] = off;
    }
    if (i == 0) g_offs[n_nodes] = E;
}

// ---------------------------------------------------------------------------
// Kernel 5: counting-sort fill. entries[pos] = (src, bits(w)), grouped by dst.
// ---------------------------------------------------------------------------
__global__ void fill_kernel(const int* __restrict__ ei,
                            const float* __restrict__ ew, int E)
{
    const int e = blockIdx.x * blockDim.x + threadIdx.x;
    if (e >= E) return;
    const int dst = ei[E + e];
    const int pos = atomicAdd(&g_cursor[dst], 1);
    g_entries[pos] = make_int2(ei[e], __float_as_int(ew[e]));
}

// ---------------------------------------------------------------------------
// Kernel 6: atomic-free aggregation. 16-lane half-warp owns one node; float4
// gathers of y rows, register accumulation, one plain RMW into out.
// ---------------------------------------------------------------------------
__global__ __launch_bounds__(256) void aggregate_kernel(
    float* __restrict__ out, int n_nodes)
{
    const int tid  = threadIdx.x;
    const int sub  = tid & 15;                       // channel chunk 0..15
    const int half = tid >> 4;                       // half-warp slot 0..15
    const int n    = blockIdx.x * 16 + half;
    if (n >= n_nodes) return;

    const int start = g_offs[n];
    const int end   = g_offs[n + 1];

    float4 acc = make_float4(0.f, 0.f, 0.f, 0.f);

    int j = start;
    for (; j + 1 < end; j += 2) {
        const int2 e0 = __ldg(&g_entries[j]);
        const int2 e1 = __ldg(&g_entries[j + 1]);
        const float w0 = __int_as_float(e0.y);
        const float w1 = __int_as_float(e1.y);
        const float4 v0 = *reinterpret_cast<const float4*>(
            g_y + (size_t)e0.x * HID + sub * 4);
        const float4 v1 = *reinterpret_cast<const float4*>(
            g_y + (size_t)e1.x * HID + sub * 4);
        acc.x = fmaf(w0, v0.x, acc.x); acc.y = fmaf(w0, v0.y, acc.y);
        acc.z = fmaf(w0, v0.z, acc.z); acc.w = fmaf(w0, v0.w, acc.w);
        acc.x = fmaf(w1, v1.x, acc.x); acc.y = fmaf(w1, v1.y, acc.y);
        acc.z = fmaf(w1, v1.z, acc.z); acc.w = fmaf(w1, v1.w, acc.w);
    }
    if (j < end) {
        const int2 e0 = __ldg(&g_entries[j]);
        const float w0 = __int_as_float(e0.y);
        const float4 v0 = *reinterpret_cast<const float4*>(
            g_y + (size_t)e0.x * HID + sub * 4);
        acc.x = fmaf(w0, v0.x, acc.x); acc.y = fmaf(w0, v0.y, acc.y);
        acc.z = fmaf(w0, v0.z, acc.z); acc.w = fmaf(w0, v0.w, acc.w);
    }

    float4* p = reinterpret_cast<float4*>(out + (size_t)n * HID + sub * 4);
    float4 o = *p;
    o.x += acc.x; o.y += acc.y; o.z += acc.z; o.w += acc.w;
    *p = o;
}

// ---------------------------------------------------------------------------
extern "C" void kernel_launch(void* const* d_in, const int* in_sizes, int n_in,
                              void* d_out, int out_size)
{
    const float* x      = (const float*)d_in[0];
    const int*   ei     = (const int*)d_in[1];
    const float* ew     = (const float*)d_in[2];
    const float* W_rel  = (const float*)d_in[3];
    const float* b_rel  = (const float*)d_in[4];
    const float* W_root = (const float*)d_in[5];
    float*       out    = (float*)d_out;

    const int n_nodes = in_sizes[0] / IN_CH;
    const int E       = in_sizes[1] / 2;   // edge_index is [2, E] int32

    const int eb      = (E + 255) / 256;
    const int n_sblks = (n_nodes + SCAN_BLK - 1) / SCAN_BLK;

    // out = W_root@x + b ; y = W_rel@x
    transform_kernel<<<2048, 64>>>(x, W_rel, b_rel, W_root, out, n_nodes);
    // CSR build
    zero_kernel<<<(n_nodes + 255) / 256, 256>>>(n_nodes);
    hist_kernel<<<eb, 256>>>(ei, E);
    scan1_kernel<<<n_sblks, SCAN_BLK>>>(n_nodes);
    scan2_kernel<<<1, SCAN_BLK>>>(n_sblks);
    scan3_kernel<<<(n_nodes + 255) / 256, 256>>>(n_nodes, E);
    fill_kernel<<<eb, 256>>>(ei, ew, E);
    // out[n] += sum_{e: dst=n} w_e * y[src_e]
    aggregate_kernel<<<(n_nodes + 15) / 16, 256>>>(out, n_nodes);
}